// round 6
// baseline (speedup 1.0000x reference)
#include <cuda_runtime.h>
#include <mma.h>
#include <cstdint>

using namespace nvcuda;

// ---------------- problem constants ----------------
#define BATCH 4
#define SEQ   2048
#define DIM   640
#define HEADS 8
#define HDIM  80
#define RANK  4
#define BS    (BATCH*SEQ)          // 8192 rows
#define BSD   (BS*DIM)             // 5,242,880 elems

// ---------------- device scratch (no allocs allowed) ----------------
__device__ float g_wq[DIM*DIM];
__device__ float g_wk[DIM*DIM];
__device__ float g_wv[DIM*DIM];
__device__ float g_wo[DIM*DIM];
__device__ float g_q[BSD];
__device__ float g_k[BSD];
__device__ float g_v[BSD];
__device__ float g_attn[BSD];

// ---------------- f32x2 packed-math helpers ----------------
__device__ __forceinline__ unsigned long long f2_pack(float lo, float hi) {
    unsigned long long r;
    asm("mov.b64 %0, {%1, %2};" : "=l"(r) : "f"(lo), "f"(hi));
    return r;
}
__device__ __forceinline__ void f2_unpack(unsigned long long v, float& lo, float& hi) {
    asm("mov.b64 {%0, %1}, %2;" : "=f"(lo), "=f"(hi) : "l"(v));
}
__device__ __forceinline__ unsigned long long f2_fma(unsigned long long a,
                                                     unsigned long long b,
                                                     unsigned long long c) {
    unsigned long long d;
    asm("fma.rn.f32x2 %0, %1, %2, %3;" : "=l"(d) : "l"(a), "l"(b), "l"(c));
    return d;
}

// ---------------- cp.async helpers (baseline PTX) ----------------
__device__ __forceinline__ uint32_t smem_u32(const void* p) {
    uint32_t a;
    asm("{ .reg .u64 t; cvta.to.shared.u64 t, %1; cvt.u32.u64 %0, t; }"
        : "=r"(a) : "l"(p));
    return a;
}
__device__ __forceinline__ void cp16(uint32_t s, const void* g) {
    asm volatile("cp.async.ca.shared.global [%0], [%1], 16;" :: "r"(s), "l"(g));
}
#define CP_COMMIT() asm volatile("cp.async.commit_group;" ::: "memory")
#define CP_WAIT(n)  asm volatile("cp.async.wait_group %0;" :: "n"(n) : "memory")

// ---------------- fold LoRA into dense weights ----------------
__global__ void fold_weights(const float* __restrict__ wq, const float* __restrict__ wk,
                             const float* __restrict__ wv, const float* __restrict__ wo,
                             const float* __restrict__ qd, const float* __restrict__ qu,
                             const float* __restrict__ kd, const float* __restrict__ ku,
                             const float* __restrict__ vd, const float* __restrict__ vu,
                             const float* __restrict__ od, const float* __restrict__ ou) {
    const float *w, *dn, *up;
    float* out;
    switch (blockIdx.y) {
        case 0:  w = wq; dn = qd; up = qu; out = g_wq; break;
        case 1:  w = wk; dn = kd; up = ku; out = g_wk; break;
        case 2:  w = wv; dn = vd; up = vu; out = g_wv; break;
        default: w = wo; dn = od; up = ou; out = g_wo; break;
    }
    int idx = blockIdx.x * blockDim.x + threadIdx.x;
    if (idx >= DIM * DIM) return;
    int o = idx / DIM;
    int i = idx - o * DIM;
    float s = w[idx];
#pragma unroll
    for (int r = 0; r < RANK; r++)
        s += up[o * RANK + r] * dn[r * DIM + i];
    out[idx] = s;
}

// ---------------- WMMA tf32 GEMM: C[8192,640] = A * W^T (+bias) ----------------
#define BK 32
#define LDS_STRIDE 40
#define TILE_FLOATS (128 * LDS_STRIDE)
#define GEMM_SMEM_BYTES (4 * TILE_FLOATS * 4)      // 81920
#define EPI_STRIDE 36

__device__ __forceinline__ void gemm_wmma_body(const float* __restrict__ A,
                                               const float* __restrict__ W,
                                               const float* __restrict__ bias,
                                               float* __restrict__ C) {
    extern __shared__ float sm[];
    float* sA[2] = { sm,               sm + 2 * TILE_FLOATS };
    float* sB[2] = { sm + TILE_FLOATS, sm + 3 * TILE_FLOATS };

    const int tid  = threadIdx.x;
    const int wid  = tid >> 5;
    const int lane = tid & 31;
    const int warp_m = wid >> 2;
    const int warp_n = wid & 3;
    const int bm = blockIdx.y;
    const int bn = blockIdx.x;

    const float* Ab = A + (size_t)bm * 128 * DIM;
    const float* Wb = W + (size_t)bn * 128 * DIM;

    const int r0 = tid >> 3;
    const int c4 = (tid & 7) * 4;

    wmma::fragment<wmma::accumulator, 16, 16, 8, float> acc[4][2];
#pragma unroll
    for (int mi = 0; mi < 4; mi++)
#pragma unroll
        for (int ni = 0; ni < 2; ni++) wmma::fill_fragment(acc[mi][ni], 0.0f);

    auto issue_stage = [&](int kt, int st) {
#pragma unroll
        for (int i = 0; i < 4; i++) {
            int row = r0 + i * 32;
            cp16(smem_u32(&sA[st][row * LDS_STRIDE + c4]),
                 Ab + (size_t)row * DIM + kt * BK + c4);
            cp16(smem_u32(&sB[st][row * LDS_STRIDE + c4]),
                 Wb + (size_t)row * DIM + kt * BK + c4);
        }
        CP_COMMIT();
    };

    issue_stage(0, 0);

    const int NKT = DIM / BK;
#pragma unroll 1
    for (int kt = 0; kt < NKT; kt++) {
        const int st = kt & 1;
        if (kt + 1 < NKT) {
            issue_stage(kt + 1, st ^ 1);
            CP_WAIT(1);
        } else {
            CP_WAIT(0);
        }
        __syncthreads();

        const float* Ac = sA[st];
        const float* Bc = sB[st];
#pragma unroll
        for (int ks = 0; ks < 4; ks++) {
            wmma::fragment<wmma::matrix_a, 16, 16, 8, wmma::precision::tf32,
                           wmma::row_major> af[4];
            wmma::fragment<wmma::matrix_b, 16, 16, 8, wmma::precision::tf32,
                           wmma::col_major> bf[2];
#pragma unroll
            for (int mi = 0; mi < 4; mi++) {
                wmma::load_matrix_sync(
                    af[mi], Ac + (warp_m * 64 + mi * 16) * LDS_STRIDE + ks * 8,
                    LDS_STRIDE);
#pragma unroll
                for (int e = 0; e < af[mi].num_elements; e++)
                    af[mi].x[e] = wmma::__float_to_tf32(af[mi].x[e]);
            }
#pragma unroll
            for (int ni = 0; ni < 2; ni++) {
                wmma::load_matrix_sync(
                    bf[ni], Bc + (warp_n * 32 + ni * 16) * LDS_STRIDE + ks * 8,
                    LDS_STRIDE);
#pragma unroll
                for (int e = 0; e < bf[ni].num_elements; e++)
                    bf[ni].x[e] = wmma::__float_to_tf32(bf[ni].x[e]);
            }
#pragma unroll
            for (int mi = 0; mi < 4; mi++)
#pragma unroll
                for (int ni = 0; ni < 2; ni++)
                    wmma::mma_sync(acc[mi][ni], af[mi], bf[ni], acc[mi][ni]);
        }
        __syncthreads();
    }

    float* stage = sm + wid * (64 * EPI_STRIDE);
#pragma unroll
    for (int mi = 0; mi < 4; mi++)
#pragma unroll
        for (int ni = 0; ni < 2; ni++)
            wmma::store_matrix_sync(stage + (mi * 16) * EPI_STRIDE + ni * 16,
                                    acc[mi][ni], EPI_STRIDE, wmma::mem_row_major);
    __syncwarp();

    const int grow = bm * 128 + warp_m * 64;
    const int gcol = bn * 128 + warp_n * 32;
#pragma unroll
    for (int i = 0; i < 16; i++) {
        int s = lane + i * 32;
        int row = s >> 3;
        int c = (s & 7) * 4;
        float4 v = *(const float4*)&stage[row * EPI_STRIDE + c];
        if (bias) {
            int n = gcol + c;
            v.x += bias[n]; v.y += bias[n + 1];
            v.z += bias[n + 2]; v.w += bias[n + 3];
        }
        *(float4*)(C + (size_t)(grow + row) * DIM + gcol + c) = v;
    }
}

__global__ void __launch_bounds__(256, 2) qkv_gemm_w(const float* __restrict__ X) {
    const float* W;
    float* C;
    if (blockIdx.z == 0)      { W = g_wq; C = g_q; }
    else if (blockIdx.z == 1) { W = g_wk; C = g_k; }
    else                      { W = g_wv; C = g_v; }
    gemm_wmma_body(X, W, nullptr, C);
}
__global__ void __launch_bounds__(256, 2) out_gemm_w(const float* __restrict__ bias,
                                                     float* __restrict__ C) {
    gemm_wmma_body(g_attn, g_wo, bias, C);
}

// ---------------- WMMA tf32 flash attention ----------------
// 128 queries x 64 keys per tile, 256 threads / 8 warps (warp w owns rows 16w..16w+15).
// Q pre-scaled by (1/sqrt(hd))*log2(e); softmax in base-2.
// smem floats: sQ[128][88] @0, sK[2][64][88] @11264, sV[2][64][88] @22528,
//              sSO[128][92] @33792 (S/P and PV-result alias), sM/sL/sC @45568+
#define QSTR 88
#define KSTR 88
#define SSTR 92
#define OFF_K0 11264
#define OFF_K1 16896
#define OFF_V0 22528
#define OFF_V1 28160
#define OFF_SO 33792
#define OFF_M  45568
#define OFF_L  45696
#define OFF_C  45824
#define FLASH_SMEM_BYTES (45952 * 4)   // 183808

__global__ void __launch_bounds__(256) flash_wmma() {
    extern __shared__ float sm[];
    float* sQ = sm;
    float* sK[2] = { sm + OFF_K0, sm + OFF_K1 };
    float* sV[2] = { sm + OFF_V0, sm + OFF_V1 };
    float* sSO = sm + OFF_SO;
    float* sM  = sm + OFF_M;
    float* sL  = sm + OFF_L;
    float* sC  = sm + OFF_C;

    const int tid  = threadIdx.x;
    const int wid  = tid >> 5;
    const int qt = blockIdx.x;   // 0..15
    const int h  = blockIdx.y;
    const int b  = blockIdx.z;

    // scale * log2(e)
    const float qscale = 0.11180339887498949f * 1.4426950408889634f;

    const size_t baseQ = ((size_t)b * SEQ + qt * 128) * DIM + h * HDIM;

    // ---- load Q (scaled), 128x80 ----
#pragma unroll
    for (int t = 0; t < 10; t++) {
        int idx = tid + t * 256;
        int r = idx / 20;
        int c = (idx % 20) * 4;
        float4 v = *(const float4*)(g_q + baseQ + (size_t)r * DIM + c);
        v.x *= qscale; v.y *= qscale; v.z *= qscale; v.w *= qscale;
        *(float4*)&sQ[r * QSTR + c] = v;
    }
    if (tid < 128) { sM[tid] = -1e30f; sL[tid] = 0.f; }

    // per-thread O slice: row = tid>>1, cols (tid&1)*40 .. +39  (20 f32x2)
    const int orow = tid >> 1;
    const int oc0  = (tid & 1) * 40;
    unsigned long long oacc[20];
#pragma unroll
    for (int j = 0; j < 20; j++) oacc[j] = 0ULL;

    auto issue_kv = [&](int kt, int st) {
        const size_t baseK = ((size_t)b * SEQ + kt * 64) * DIM + h * HDIM;
#pragma unroll
        for (int t = 0; t < 5; t++) {
            int idx = tid + t * 256;
            int r = idx / 20;
            int c = (idx % 20) * 4;
            cp16(smem_u32(&sK[st][r * KSTR + c]), g_k + baseK + (size_t)r * DIM + c);
            cp16(smem_u32(&sV[st][r * KSTR + c]), g_v + baseK + (size_t)r * DIM + c);
        }
        CP_COMMIT();
    };

    issue_kv(0, 0);

#pragma unroll 1
    for (int kt = 0; kt < SEQ / 64; kt++) {
        const int cur = kt & 1;
        CP_WAIT(0);
        __syncthreads();    // KV[cur] ready; prior iter's reads of KV[cur^1] and sSO done
        if (kt + 1 < SEQ / 64) issue_kv(kt + 1, cur ^ 1);

        // ---- S(16 rows x 64 keys per warp) = Q K^T ----
        {
            wmma::fragment<wmma::accumulator, 16, 16, 8, float> sacc[4];
#pragma unroll
            for (int j = 0; j < 4; j++) wmma::fill_fragment(sacc[j], 0.0f);
#pragma unroll
            for (int ks = 0; ks < 10; ks++) {
                wmma::fragment<wmma::matrix_a, 16, 16, 8, wmma::precision::tf32,
                               wmma::row_major> af;
                wmma::load_matrix_sync(af, sQ + wid * 16 * QSTR + ks * 8, QSTR);
#pragma unroll
                for (int e = 0; e < af.num_elements; e++)
                    af.x[e] = wmma::__float_to_tf32(af.x[e]);
#pragma unroll
                for (int j = 0; j < 4; j++) {
                    wmma::fragment<wmma::matrix_b, 16, 16, 8, wmma::precision::tf32,
                                   wmma::col_major> bf;
                    wmma::load_matrix_sync(bf, sK[cur] + j * 16 * KSTR + ks * 8, KSTR);
#pragma unroll
                    for (int e = 0; e < bf.num_elements; e++)
                        bf.x[e] = wmma::__float_to_tf32(bf.x[e]);
                    wmma::mma_sync(sacc[j], af, bf, sacc[j]);
                }
            }
#pragma unroll
            for (int j = 0; j < 4; j++)
                wmma::store_matrix_sync(sSO + wid * 16 * SSTR + j * 16, sacc[j],
                                        SSTR, wmma::mem_row_major);
        }
        __syncthreads();

        // ---- online softmax (base 2), one row per thread, float4 reads ----
        if (tid < 128) {
            float* row = sSO + tid * SSTR;
            float mo = sM[tid];
            float mx = mo;
#pragma unroll
            for (int j4 = 0; j4 < 16; j4++) {
                float4 v = *(const float4*)&row[j4 * 4];
                mx = fmaxf(mx, fmaxf(fmaxf(v.x, v.y), fmaxf(v.z, v.w)));
            }
            float corr = exp2f(mo - mx);
            float sum = 0.f;
#pragma unroll
            for (int j4 = 0; j4 < 16; j4++) {
                float4 v = *(const float4*)&row[j4 * 4];
                v.x = exp2f(v.x - mx); v.y = exp2f(v.y - mx);
                v.z = exp2f(v.z - mx); v.w = exp2f(v.w - mx);
                sum += (v.x + v.y) + (v.z + v.w);
                *(float4*)&row[j4 * 4] = v;
            }
            sL[tid] = sL[tid] * corr + sum;
            sM[tid] = mx;
            sC[tid] = corr;
        }
        __syncthreads();

        // ---- PV: O_tile(16 x 80 per warp) = P(16x64) @ V(64x80) ----
        {
            wmma::fragment<wmma::accumulator, 16, 16, 8, float> oacc_f[5];
#pragma unroll
            for (int n = 0; n < 5; n++) wmma::fill_fragment(oacc_f[n], 0.0f);
#pragma unroll
            for (int ks = 0; ks < 8; ks++) {
                wmma::fragment<wmma::matrix_a, 16, 16, 8, wmma::precision::tf32,
                               wmma::row_major> af;
                wmma::load_matrix_sync(af, sSO + wid * 16 * SSTR + ks * 8, SSTR);
#pragma unroll
                for (int e = 0; e < af.num_elements; e++)
                    af.x[e] = wmma::__float_to_tf32(af.x[e]);
#pragma unroll
                for (int n = 0; n < 5; n++) {
                    wmma::fragment<wmma::matrix_b, 16, 16, 8, wmma::precision::tf32,
                                   wmma::row_major> bf;
                    wmma::load_matrix_sync(bf, sV[cur] + ks * 8 * KSTR + n * 16, KSTR);
#pragma unroll
                    for (int e = 0; e < bf.num_elements; e++)
                        bf.x[e] = wmma::__float_to_tf32(bf.x[e]);
                    wmma::mma_sync(oacc_f[n], af, bf, oacc_f[n]);
                }
            }
            // alias store into own warp's rows of sSO (P fully consumed by this warp)
#pragma unroll
            for (int n = 0; n < 5; n++)
                wmma::store_matrix_sync(sSO + wid * 16 * SSTR + n * 16, oacc_f[n],
                                        SSTR, wmma::mem_row_major);
        }
        __syncwarp();

        // ---- O = O*corr + PV_tile (own warp's rows only) ----
        {
            float corr = sC[orow];
            unsigned long long corr2 = f2_pack(corr, corr);
            const float* prow = sSO + orow * SSTR + oc0;
#pragma unroll
            for (int j = 0; j < 20; j++) {
                unsigned long long pv = *(const unsigned long long*)(prow + 2 * j);
                oacc[j] = f2_fma(oacc[j], corr2, pv);
            }
        }
    }

    // ---- epilogue ----
    {
        float inv = 1.f / sL[orow];
        unsigned long long inv2 = f2_pack(inv, inv);
        size_t o = ((size_t)b * SEQ + qt * 128 + orow) * DIM + h * HDIM + oc0;
#pragma unroll
        for (int j = 0; j < 20; j++) {
            float lo, hi;
            unsigned long long r;
            asm("mul.rn.f32x2 %0, %1, %2;" : "=l"(r) : "l"(oacc[j]), "l"(inv2));
            f2_unpack(r, lo, hi);
            *(float2*)(g_attn + o + 2 * j) = make_float2(lo, hi);
        }
    }
}

// ---------------- launch ----------------
extern "C" void kernel_launch(void* const* d_in, const int* in_sizes, int n_in,
                              void* d_out, int out_size) {
    (void)in_sizes; (void)n_in; (void)out_size;
    const float* x  = (const float*)d_in[0];
    const float* wq = (const float*)d_in[1];
    const float* wk = (const float*)d_in[2];
    const float* wv = (const float*)d_in[3];
    const float* wo = (const float*)d_in[4];
    const float* bo = (const float*)d_in[5];
    const float* qd = (const float*)d_in[6];
    const float* qu = (const float*)d_in[7];
    const float* kd = (const float*)d_in[8];
    const float* ku = (const float*)d_in[9];
    const float* vd = (const float*)d_in[10];
    const float* vu = (const float*)d_in[11];
    const float* od = (const float*)d_in[12];
    const float* ou = (const float*)d_in[13];
    float* out = (float*)d_out;

    fold_weights<<<dim3((DIM * DIM + 255) / 256, 4), 256>>>(
        wq, wk, wv, wo, qd, qu, kd, ku, vd, vu, od, ou);

    cudaFuncSetAttribute(qkv_gemm_w, cudaFuncAttributeMaxDynamicSharedMemorySize,
                         GEMM_SMEM_BYTES);
    qkv_gemm_w<<<dim3(DIM / 128, BS / 128, 3), 256, GEMM_SMEM_BYTES>>>(x);

    cudaFuncSetAttribute(flash_wmma, cudaFuncAttributeMaxDynamicSharedMemorySize,
                         FLASH_SMEM_BYTES);
    flash_wmma<<<dim3(SEQ / 128, HEADS, BATCH), 256, FLASH_SMEM_BYTES>>>();

    cudaFuncSetAttribute(out_gemm_w, cudaFuncAttributeMaxDynamicSharedMemorySize,
                         GEMM_SMEM_BYTES);
    out_gemm_w<<<dim3(DIM / 128, BS / 128), 256, GEMM_SMEM_BYTES>>>(bo, out);
}

// round 8
// speedup vs baseline: 1.6469x; 1.6469x over previous
#include <cuda_runtime.h>
#include <mma.h>
#include <cstdint>

using namespace nvcuda;

// ---------------- problem constants ----------------
#define BATCH 4
#define SEQ   2048
#define DIM   640
#define HEADS 8
#define HDIM  80
#define RANK  4
#define BS    (BATCH*SEQ)          // 8192 rows
#define BSD   (BS*DIM)             // 5,242,880 elems

// ---------------- device scratch (no allocs allowed) ----------------
__device__ float g_wq[DIM*DIM];
__device__ float g_wk[DIM*DIM];
__device__ float g_wv[DIM*DIM];
__device__ float g_wo[DIM*DIM];
__device__ float g_q[BSD];
__device__ float g_k[BSD];
__device__ float g_v[BSD];
__device__ float g_attn[BSD];   // holds tf32(x) during qkv, then attention output

// ---------------- helpers ----------------
__device__ __forceinline__ float tf32r(float f) {
    uint32_t u;
    asm("cvt.rna.tf32.f32 %0, %1;" : "=r"(u) : "f"(f));
    return __uint_as_float(u);
}
__device__ __forceinline__ unsigned long long f2_pack(float lo, float hi) {
    unsigned long long r;
    asm("mov.b64 %0, {%1, %2};" : "=l"(r) : "f"(lo), "f"(hi));
    return r;
}
__device__ __forceinline__ void f2_unpack(unsigned long long v, float& lo, float& hi) {
    asm("mov.b64 {%0, %1}, %2;" : "=f"(lo), "=f"(hi) : "l"(v));
}
__device__ __forceinline__ unsigned long long f2_fma(unsigned long long a,
                                                     unsigned long long b,
                                                     unsigned long long c) {
    unsigned long long d;
    asm("fma.rn.f32x2 %0, %1, %2, %3;" : "=l"(d) : "l"(a), "l"(b), "l"(c));
    return d;
}
__device__ __forceinline__ uint32_t smem_u32(const void* p) {
    uint32_t a;
    asm("{ .reg .u64 t; cvta.to.shared.u64 t, %1; cvt.u32.u64 %0, t; }"
        : "=r"(a) : "l"(p));
    return a;
}
__device__ __forceinline__ void cp16(uint32_t s, const void* g) {
    asm volatile("cp.async.ca.shared.global [%0], [%1], 16;" :: "r"(s), "l"(g));
}
#define CP_COMMIT() asm volatile("cp.async.commit_group;" ::: "memory")
#define CP_WAIT(n)  asm volatile("cp.async.wait_group %0;" :: "n"(n) : "memory")

// ---------------- fold LoRA into dense weights (tf32-rounded output) ----------------
__global__ void fold_weights(const float* __restrict__ wq, const float* __restrict__ wk,
                             const float* __restrict__ wv, const float* __restrict__ wo,
                             const float* __restrict__ qd, const float* __restrict__ qu,
                             const float* __restrict__ kd, const float* __restrict__ ku,
                             const float* __restrict__ vd, const float* __restrict__ vu,
                             const float* __restrict__ od, const float* __restrict__ ou) {
    const float *w, *dn, *up;
    float* out;
    switch (blockIdx.y) {
        case 0:  w = wq; dn = qd; up = qu; out = g_wq; break;
        case 1:  w = wk; dn = kd; up = ku; out = g_wk; break;
        case 2:  w = wv; dn = vd; up = vu; out = g_wv; break;
        default: w = wo; dn = od; up = ou; out = g_wo; break;
    }
    int idx = blockIdx.x * blockDim.x + threadIdx.x;
    if (idx >= DIM * DIM) return;
    int o = idx / DIM;
    int i = idx - o * DIM;
    float s = w[idx];
#pragma unroll
    for (int r = 0; r < RANK; r++)
        s += up[o * RANK + r] * dn[r * DIM + i];
    out[idx] = tf32r(s);
}

// ---------------- round x -> tf32 into g_attn (scratch reuse) ----------------
__global__ void round_x(const float* __restrict__ x) {
    int i = (blockIdx.x * blockDim.x + threadIdx.x) * 4;
    if (i >= BSD) return;
    float4 v = *(const float4*)(x + i);
    v.x = tf32r(v.x); v.y = tf32r(v.y); v.z = tf32r(v.z); v.w = tf32r(v.w);
    *(float4*)(g_attn + i) = v;
}

// ---------------- WMMA tf32 GEMM: C = A * W^T (+bias); data already tf32 ----------
#define BK 32
#define LDS_STRIDE 40
#define TILE_FLOATS (128 * LDS_STRIDE)
#define GEMM_SMEM_BYTES (4 * TILE_FLOATS * 4)      // 81920
#define EPI_STRIDE 36

template <bool ROUND_OUT>
__device__ __forceinline__ void gemm_wmma_body(const float* __restrict__ A,
                                               const float* __restrict__ W,
                                               const float* __restrict__ bias,
                                               float* __restrict__ C) {
    extern __shared__ float sm[];
    float* sA[2] = { sm,               sm + 2 * TILE_FLOATS };
    float* sB[2] = { sm + TILE_FLOATS, sm + 3 * TILE_FLOATS };

    const int tid  = threadIdx.x;
    const int wid  = tid >> 5;
    const int lane = tid & 31;
    const int warp_m = wid >> 2;
    const int warp_n = wid & 3;
    const int bm = blockIdx.y;
    const int bn = blockIdx.x;

    const float* Ab = A + (size_t)bm * 128 * DIM;
    const float* Wb = W + (size_t)bn * 128 * DIM;

    const int r0 = tid >> 3;
    const int c4 = (tid & 7) * 4;

    wmma::fragment<wmma::accumulator, 16, 16, 8, float> acc[4][2];
#pragma unroll
    for (int mi = 0; mi < 4; mi++)
#pragma unroll
        for (int ni = 0; ni < 2; ni++) wmma::fill_fragment(acc[mi][ni], 0.0f);

    auto issue_stage = [&](int kt, int st) {
#pragma unroll
        for (int i = 0; i < 4; i++) {
            int row = r0 + i * 32;
            cp16(smem_u32(&sA[st][row * LDS_STRIDE + c4]),
                 Ab + (size_t)row * DIM + kt * BK + c4);
            cp16(smem_u32(&sB[st][row * LDS_STRIDE + c4]),
                 Wb + (size_t)row * DIM + kt * BK + c4);
        }
        CP_COMMIT();
    };

    issue_stage(0, 0);

    const int NKT = DIM / BK;
#pragma unroll 1
    for (int kt = 0; kt < NKT; kt++) {
        const int st = kt & 1;
        if (kt + 1 < NKT) {
            issue_stage(kt + 1, st ^ 1);
            CP_WAIT(1);
        } else {
            CP_WAIT(0);
        }
        __syncthreads();

        const float* Ac = sA[st];
        const float* Bc = sB[st];
#pragma unroll
        for (int ks = 0; ks < 4; ks++) {
            wmma::fragment<wmma::matrix_a, 16, 16, 8, wmma::precision::tf32,
                           wmma::row_major> af[4];
            wmma::fragment<wmma::matrix_b, 16, 16, 8, wmma::precision::tf32,
                           wmma::col_major> bf[2];
#pragma unroll
            for (int mi = 0; mi < 4; mi++)
                wmma::load_matrix_sync(
                    af[mi], Ac + (warp_m * 64 + mi * 16) * LDS_STRIDE + ks * 8,
                    LDS_STRIDE);
#pragma unroll
            for (int ni = 0; ni < 2; ni++)
                wmma::load_matrix_sync(
                    bf[ni], Bc + (warp_n * 32 + ni * 16) * LDS_STRIDE + ks * 8,
                    LDS_STRIDE);
#pragma unroll
            for (int mi = 0; mi < 4; mi++)
#pragma unroll
                for (int ni = 0; ni < 2; ni++)
                    wmma::mma_sync(acc[mi][ni], af[mi], bf[ni], acc[mi][ni]);
        }
        __syncthreads();
    }

    float* stage = sm + wid * (64 * EPI_STRIDE);
#pragma unroll
    for (int mi = 0; mi < 4; mi++)
#pragma unroll
        for (int ni = 0; ni < 2; ni++)
            wmma::store_matrix_sync(stage + (mi * 16) * EPI_STRIDE + ni * 16,
                                    acc[mi][ni], EPI_STRIDE, wmma::mem_row_major);
    __syncwarp();

    const int grow = bm * 128 + warp_m * 64;
    const int gcol = bn * 128 + warp_n * 32;
#pragma unroll
    for (int i = 0; i < 16; i++) {
        int s = lane + i * 32;
        int row = s >> 3;
        int c = (s & 7) * 4;
        float4 v = *(const float4*)&stage[row * EPI_STRIDE + c];
        if (bias) {
            int n = gcol + c;
            v.x += bias[n]; v.y += bias[n + 1];
            v.z += bias[n + 2]; v.w += bias[n + 3];
        }
        if (ROUND_OUT) {
            v.x = tf32r(v.x); v.y = tf32r(v.y);
            v.z = tf32r(v.z); v.w = tf32r(v.w);
        }
        *(float4*)(C + (size_t)(grow + row) * DIM + gcol + c) = v;
    }
}

__global__ void __launch_bounds__(256) qkv_gemm_w() {
    const float* W;
    float* C;
    if (blockIdx.z == 0)      { W = g_wq; C = g_q; }
    else if (blockIdx.z == 1) { W = g_wk; C = g_k; }
    else                      { W = g_wv; C = g_v; }
    gemm_wmma_body<true>(g_attn /* tf32(x) */, W, nullptr, C);
}
__global__ void __launch_bounds__(256) out_gemm_w(const float* __restrict__ bias,
                                                  float* __restrict__ C) {
    gemm_wmma_body<false>(g_attn, g_wo, bias, C);
}

// ---------------- WMMA tf32 flash attention (data tf32-at-rest, zero in-loop cvt) --
// 128 queries x 64 keys per tile, 256 threads / 8 warps (warp w owns rows 16w..16w+15).
// Softmax in base-2 with sm_scale*log2e applied to scores inside softmax.
#define QSTR 88
#define KSTR 88
#define SSTR 92
#define OFF_K0 11264
#define OFF_K1 16896
#define OFF_V0 22528
#define OFF_V1 28160
#define OFF_SO 33792
#define OFF_M  45568
#define OFF_L  45696
#define OFF_C  45824
#define FLASH_SMEM_BYTES (45952 * 4)   // 183808

__global__ void __launch_bounds__(256) flash_wmma() {
    extern __shared__ float sm[];
    float* sQ = sm;
    float* sK[2] = { sm + OFF_K0, sm + OFF_K1 };
    float* sV[2] = { sm + OFF_V0, sm + OFF_V1 };
    float* sSO = sm + OFF_SO;
    float* sM  = sm + OFF_M;
    float* sL  = sm + OFF_L;
    float* sC  = sm + OFF_C;

    const int tid  = threadIdx.x;
    const int wid  = tid >> 5;
    const int qt = blockIdx.x;   // 0..15
    const int h  = blockIdx.y;
    const int b  = blockIdx.z;

    // sm_scale * log2(e), applied to raw scores inside softmax
    const float qs2 = 0.11180339887498949f * 1.4426950408889634f;

    const size_t baseQ = ((size_t)b * SEQ + qt * 128) * DIM + h * HDIM;

    // ---- load Q (already tf32), 128x80 ----
#pragma unroll
    for (int t = 0; t < 10; t++) {
        int idx = tid + t * 256;
        int r = idx / 20;
        int c = (idx % 20) * 4;
        *(float4*)&sQ[r * QSTR + c] =
            *(const float4*)(g_q + baseQ + (size_t)r * DIM + c);
    }
    if (tid < 128) { sM[tid] = -1e30f; sL[tid] = 0.f; }

    const int orow = tid >> 1;
    const int oc0  = (tid & 1) * 40;
    unsigned long long oacc[20];
#pragma unroll
    for (int j = 0; j < 20; j++) oacc[j] = 0ULL;

    auto issue_kv = [&](int kt, int st) {
        const size_t baseK = ((size_t)b * SEQ + kt * 64) * DIM + h * HDIM;
#pragma unroll
        for (int t = 0; t < 5; t++) {
            int idx = tid + t * 256;
            int r = idx / 20;
            int c = (idx % 20) * 4;
            cp16(smem_u32(&sK[st][r * KSTR + c]), g_k + baseK + (size_t)r * DIM + c);
            cp16(smem_u32(&sV[st][r * KSTR + c]), g_v + baseK + (size_t)r * DIM + c);
        }
        CP_COMMIT();
    };

    issue_kv(0, 0);

#pragma unroll 1
    for (int kt = 0; kt < SEQ / 64; kt++) {
        const int cur = kt & 1;
        CP_WAIT(0);
        __syncthreads();
        if (kt + 1 < SEQ / 64) issue_kv(kt + 1, cur ^ 1);

        // ---- S(16 rows x 64 keys per warp) = Q K^T  (no cvt: inputs tf32) ----
        {
            wmma::fragment<wmma::accumulator, 16, 16, 8, float> sacc[4];
#pragma unroll
            for (int j = 0; j < 4; j++) wmma::fill_fragment(sacc[j], 0.0f);
#pragma unroll
            for (int ks = 0; ks < 10; ks++) {
                wmma::fragment<wmma::matrix_a, 16, 16, 8, wmma::precision::tf32,
                               wmma::row_major> af;
                wmma::load_matrix_sync(af, sQ + wid * 16 * QSTR + ks * 8, QSTR);
#pragma unroll
                for (int j = 0; j < 4; j++) {
                    wmma::fragment<wmma::matrix_b, 16, 16, 8, wmma::precision::tf32,
                                   wmma::col_major> bf;
                    wmma::load_matrix_sync(bf, sK[cur] + j * 16 * KSTR + ks * 8, KSTR);
                    wmma::mma_sync(sacc[j], af, bf, sacc[j]);
                }
            }
#pragma unroll
            for (int j = 0; j < 4; j++)
                wmma::store_matrix_sync(sSO + wid * 16 * SSTR + j * 16, sacc[j],
                                        SSTR, wmma::mem_row_major);
        }
        __syncthreads();

        // ---- online softmax (base 2, scale folded in); P stored tf32-rounded ----
        if (tid < 128) {
            float* row = sSO + tid * SSTR;
            float mo = sM[tid];
            float mx = mo;
#pragma unroll
            for (int j4 = 0; j4 < 16; j4++) {
                float4 v = *(const float4*)&row[j4 * 4];
                v.x *= qs2; v.y *= qs2; v.z *= qs2; v.w *= qs2;
                mx = fmaxf(mx, fmaxf(fmaxf(v.x, v.y), fmaxf(v.z, v.w)));
                *(float4*)&row[j4 * 4] = v;
            }
            float corr = exp2f(mo - mx);
            float sum = 0.f;
#pragma unroll
            for (int j4 = 0; j4 < 16; j4++) {
                float4 v = *(const float4*)&row[j4 * 4];
                v.x = tf32r(exp2f(v.x - mx)); v.y = tf32r(exp2f(v.y - mx));
                v.z = tf32r(exp2f(v.z - mx)); v.w = tf32r(exp2f(v.w - mx));
                sum += (v.x + v.y) + (v.z + v.w);
                *(float4*)&row[j4 * 4] = v;
            }
            sL[tid] = sL[tid] * corr + sum;
            sM[tid] = mx;
            sC[tid] = corr;
        }
        __syncthreads();

        // ---- PV: O_tile(16 x 80 per warp) = P(16x64) @ V(64x80)  (no cvt) ----
        {
            wmma::fragment<wmma::accumulator, 16, 16, 8, float> of[5];
#pragma unroll
            for (int n = 0; n < 5; n++) wmma::fill_fragment(of[n], 0.0f);
#pragma unroll
            for (int ks = 0; ks < 8; ks++) {
                wmma::fragment<wmma::matrix_a, 16, 16, 8, wmma::precision::tf32,
                               wmma::row_major> af;
                wmma::load_matrix_sync(af, sSO + wid * 16 * SSTR + ks * 8, SSTR);
#pragma unroll
                for (int n = 0; n < 5; n++) {
                    wmma::fragment<wmma::matrix_b, 16, 16, 8, wmma::precision::tf32,
                                   wmma::row_major> bf;
                    wmma::load_matrix_sync(bf, sV[cur] + ks * 8 * KSTR + n * 16, KSTR);
                    wmma::mma_sync(of[n], af, bf, of[n]);
                }
            }
#pragma unroll
            for (int n = 0; n < 5; n++)
                wmma::store_matrix_sync(sSO + wid * 16 * SSTR + n * 16, of[n],
                                        SSTR, wmma::mem_row_major);
        }
        __syncwarp();

        // ---- O = O*corr + PV_tile (own warp's rows only) ----
        {
            float corr = sC[orow];
            unsigned long long corr2 = f2_pack(corr, corr);
            const float* prow = sSO + orow * SSTR + oc0;
#pragma unroll
            for (int j = 0; j < 20; j++) {
                unsigned long long pv = *(const unsigned long long*)(prow + 2 * j);
                oacc[j] = f2_fma(oacc[j], corr2, pv);
            }
        }
    }

    // ---- epilogue: normalize, round to tf32 (feeds out_gemm), store ----
    {
        float inv = 1.f / sL[orow];
        size_t o = ((size_t)b * SEQ + qt * 128 + orow) * DIM + h * HDIM + oc0;
#pragma unroll
        for (int j = 0; j < 20; j++) {
            float lo, hi;
            f2_unpack(oacc[j], lo, hi);
            *(float2*)(g_attn + o + 2 * j) =
                make_float2(tf32r(lo * inv), tf32r(hi * inv));
        }
    }
}

// ---------------- launch ----------------
extern "C" void kernel_launch(void* const* d_in, const int* in_sizes, int n_in,
                              void* d_out, int out_size) {
    (void)in_sizes; (void)n_in; (void)out_size;
    const float* x  = (const float*)d_in[0];
    const float* wq = (const float*)d_in[1];
    const float* wk = (const float*)d_in[2];
    const float* wv = (const float*)d_in[3];
    const float* wo = (const float*)d_in[4];
    const float* bo = (const float*)d_in[5];
    const float* qd = (const float*)d_in[6];
    const float* qu = (const float*)d_in[7];
    const float* kd = (const float*)d_in[8];
    const float* ku = (const float*)d_in[9];
    const float* vd = (const float*)d_in[10];
    const float* vu = (const float*)d_in[11];
    const float* od = (const float*)d_in[12];
    const float* ou = (const float*)d_in[13];
    float* out = (float*)d_out;

    fold_weights<<<dim3((DIM * DIM + 255) / 256, 4), 256>>>(
        wq, wk, wv, wo, qd, qu, kd, ku, vd, vu, od, ou);

    round_x<<<(BSD / 4 + 255) / 256, 256>>>(x);

    cudaFuncSetAttribute(qkv_gemm_w, cudaFuncAttributeMaxDynamicSharedMemorySize,
                         GEMM_SMEM_BYTES);
    qkv_gemm_w<<<dim3(DIM / 128, BS / 128, 3), 256, GEMM_SMEM_BYTES>>>();

    cudaFuncSetAttribute(flash_wmma, cudaFuncAttributeMaxDynamicSharedMemorySize,
                         FLASH_SMEM_BYTES);
    flash_wmma<<<dim3(SEQ / 128, HEADS, BATCH), 256, FLASH_SMEM_BYTES>>>();

    cudaFuncSetAttribute(out_gemm_w, cudaFuncAttributeMaxDynamicSharedMemorySize,
                         GEMM_SMEM_BYTES);
    out_gemm_w<<<dim3(DIM / 128, BS / 128), 256, GEMM_SMEM_BYTES>>>(bo, out);
}